// round 6
// baseline (speedup 1.0000x reference)
#include <cuda_runtime.h>
#include <cstdint>

// ProbabilityAdjustedLoss: B=8388608 rows, logits[B,2] fp32, labels[B] int32
// (confirmed int32: int64-width loads faulted in R1; JAX x64-disabled).
// p = softmax(logits); label==0: loss=-w0*log(p0+eps), else -w1*log(p1+eps)
// out = mean(loss)

#define B_TOTAL 8388608
#define NPAIRS  (B_TOTAL / 2)          // 2 rows per iteration (float4 + int2)
#define GRID1   2048
#define BLK1    256

__device__ float g_partials[GRID1];

__device__ __forceinline__ float row_loss(float l0, float l1, int lab) {
    // p1 = sigmoid(l1 - l0), p0 = 1 - p1
    float d  = l1 - l0;
    float p1 = __fdividef(1.0f, 1.0f + __expf(-d));
    float p0 = 1.0f - p1;
    if (lab == 0) {
        // adj0 = max(0, p0-0.95)/0.05 ; w0 = max(0.1, 1 - 0.5*adj0)
        float adj0 = fmaxf(0.0f, p0 - 0.95f) * 20.0f;
        float w0   = fmaxf(0.1f, 1.0f - 0.5f * adj0);
        return -w0 * __logf(p0 + 1e-8f);
    } else {
        float adj1 = fmaxf(0.0f, p1 - 0.05f) * (1.0f / 0.95f);
        float w1   = fmaxf(0.5f, 2.0f - adj1);
        return -w1 * __logf(p1 + 1e-8f);
    }
}

__global__ void __launch_bounds__(BLK1)
loss_stage1(const float4* __restrict__ logits2,   // [NPAIRS] : 2 rows per float4
            const int2*   __restrict__ labels2,   // [NPAIRS] : 2 int32 labels per vec
            int npairs) {
    float acc = 0.0f;
    int stride = gridDim.x * blockDim.x;
    for (int i = blockIdx.x * blockDim.x + threadIdx.x; i < npairs; i += stride) {
        float4 lg = logits2[i];
        int2   lb = labels2[i];
        acc += row_loss(lg.x, lg.y, lb.x);
        acc += row_loss(lg.z, lg.w, lb.y);
    }

    // warp reduce
    #pragma unroll
    for (int off = 16; off > 0; off >>= 1)
        acc += __shfl_xor_sync(0xFFFFFFFFu, acc, off);

    __shared__ float warp_sums[BLK1 / 32];
    int lane = threadIdx.x & 31;
    int wid  = threadIdx.x >> 5;
    if (lane == 0) warp_sums[wid] = acc;
    __syncthreads();

    if (wid == 0) {
        float v = (lane < BLK1 / 32) ? warp_sums[lane] : 0.0f;
        #pragma unroll
        for (int off = 16; off > 0; off >>= 1)
            v += __shfl_xor_sync(0xFFFFFFFFu, v, off);
        if (lane == 0) g_partials[blockIdx.x] = v;
    }
}

__global__ void __launch_bounds__(1024)
loss_stage2(float* __restrict__ out) {
    double acc = 0.0;
    for (int i = threadIdx.x; i < GRID1; i += 1024)
        acc += (double)g_partials[i];

    #pragma unroll
    for (int off = 16; off > 0; off >>= 1)
        acc += __shfl_xor_sync(0xFFFFFFFFu, acc, off);

    __shared__ double warp_sums[32];
    int lane = threadIdx.x & 31;
    int wid  = threadIdx.x >> 5;
    if (lane == 0) warp_sums[wid] = acc;
    __syncthreads();

    if (wid == 0) {
        double v = (lane < 32) ? warp_sums[lane] : 0.0;
        #pragma unroll
        for (int off = 16; off > 0; off >>= 1)
            v += __shfl_xor_sync(0xFFFFFFFFu, v, off);
        if (lane == 0)
            out[0] = (float)(v / (double)B_TOTAL);
    }
}

extern "C" void kernel_launch(void* const* d_in, const int* in_sizes, int n_in,
                              void* d_out, int out_size) {
    const float4* logits2 = (const float4*)d_in[0];
    const int2*   labels2 = (const int2*)d_in[1];
    float* out = (float*)d_out;

    loss_stage1<<<GRID1, BLK1>>>(logits2, labels2, NPAIRS);
    loss_stage2<<<1, 1024>>>(out);
}

// round 8
// speedup vs baseline: 1.0655x; 1.0655x over previous
#include <cuda_runtime.h>
#include <cstdint>

// ProbabilityAdjustedLoss: B=8388608 rows, logits[B,2] fp32, labels[B] int32.
// Fused single-kernel: grid-stride partial sums + last-block-done final
// reduction (deterministic: fixed-order fp64 sum of 2048 fp32 partials).
// Counter self-resets to 0 so CUDA-graph replays are identical.

#define B_TOTAL 8388608
#define NPAIRS  (B_TOTAL / 2)          // 2 rows per iteration (float4 + int2)
#define GRID1   2048
#define BLK1    256

__device__ float        g_partials[GRID1];
__device__ unsigned int g_counter = 0;

__device__ __forceinline__ float row_loss(float l0, float l1, int lab) {
    // p1 = sigmoid(l1 - l0), p0 = 1 - p1
    float d  = l1 - l0;
    float p1 = __fdividef(1.0f, 1.0f + __expf(-d));
    float p0 = 1.0f - p1;
    if (lab == 0) {
        float adj0 = fmaxf(0.0f, p0 - 0.95f) * 20.0f;
        float w0   = fmaxf(0.1f, 1.0f - 0.5f * adj0);
        return -w0 * __logf(p0 + 1e-8f);
    } else {
        float adj1 = fmaxf(0.0f, p1 - 0.05f) * (1.0f / 0.95f);
        float w1   = fmaxf(0.5f, 2.0f - adj1);
        return -w1 * __logf(p1 + 1e-8f);
    }
}

__global__ void __launch_bounds__(BLK1)
loss_fused(const float4* __restrict__ logits2,   // [NPAIRS] : 2 rows per float4
           const int2*   __restrict__ labels2,   // [NPAIRS] : 2 int32 labels per vec
           float* __restrict__ out) {
    float acc = 0.0f;
    int stride = gridDim.x * blockDim.x;
    for (int i = blockIdx.x * blockDim.x + threadIdx.x; i < NPAIRS; i += stride) {
        float4 lg = logits2[i];
        int2   lb = labels2[i];
        acc += row_loss(lg.x, lg.y, lb.x);
        acc += row_loss(lg.z, lg.w, lb.y);
    }

    // intra-block reduce (fp32 partial; fine — fp64 happens on partials below)
    #pragma unroll
    for (int off = 16; off > 0; off >>= 1)
        acc += __shfl_xor_sync(0xFFFFFFFFu, acc, off);

    __shared__ float warp_sums[BLK1 / 32];
    int lane = threadIdx.x & 31;
    int wid  = threadIdx.x >> 5;
    if (lane == 0) warp_sums[wid] = acc;
    __syncthreads();

    __shared__ bool is_last;
    if (wid == 0) {
        float v = (lane < BLK1 / 32) ? warp_sums[lane] : 0.0f;
        #pragma unroll
        for (int off = 16; off > 0; off >>= 1)
            v += __shfl_xor_sync(0xFFFFFFFFu, v, off);
        if (lane == 0) {
            g_partials[blockIdx.x] = v;
            __threadfence();                      // partial visible before count
            unsigned int done = atomicAdd(&g_counter, 1u);
            is_last = (done == GRID1 - 1);
        }
    }
    __syncthreads();

    if (!is_last) return;

    // Final block: deterministic fixed-order fp64 reduction of all partials.
    double dacc = 0.0;
    for (int i = threadIdx.x; i < GRID1; i += BLK1)
        dacc += (double)g_partials[i];

    #pragma unroll
    for (int off = 16; off > 0; off >>= 1)
        dacc += __shfl_xor_sync(0xFFFFFFFFu, dacc, off);

    __shared__ double dwarp[BLK1 / 32];
    if (lane == 0) dwarp[wid] = dacc;
    __syncthreads();

    if (wid == 0) {
        double v = (lane < BLK1 / 32) ? dwarp[lane] : 0.0;
        #pragma unroll
        for (int off = 16; off > 0; off >>= 1)
            v += __shfl_xor_sync(0xFFFFFFFFu, v, off);
        if (lane == 0) {
            out[0] = (float)(v / (double)B_TOTAL);
            g_counter = 0;                        // reset for next graph replay
        }
    }
}

extern "C" void kernel_launch(void* const* d_in, const int* in_sizes, int n_in,
                              void* d_out, int out_size) {
    const float4* logits2 = (const float4*)d_in[0];
    const int2*   labels2 = (const int2*)d_in[1];
    float* out = (float*)d_out;

    loss_fused<<<GRID1, BLK1>>>(logits2, labels2, out);
}